// round 13
// baseline (speedup 1.0000x reference)
#include <cuda_runtime.h>
#include <math.h>
#include <float.h>
#include <stdint.h>
#include <cuda_fp16.h>

#define KCOMP 32
#define DDIM  128
#define LDIM  4
#define TPB   512
#define ROWS_TILE 256

// smem byte offsets (~185KB, 1 CTA/SM, 512 threads)
#define SM_W   0         // weights: 192 rows x 256B (fp16) = 49152
#define SM_X0  49152     // x tile buffer 0: 256 x 256B = 65536
#define SM_X1  114688    // x tile buffer 1
#define SM_C   180224    // cst[32] + bm[4][32] floats = 640
#define SM_P   180864    // sP: 2 x 512 float2 = 8192
#define SMEM_TOTAL 189056

// ---- helpers --------------------------------------------------------------
__device__ __forceinline__ uint32_t h2pack(float a, float b) {
    __half2 h = __floats2half2_rn(a, b);
    return *(uint32_t*)&h;
}
__device__ __forceinline__ uint32_t smem_u32(const void* p) {
    uint32_t a;
    asm("{ .reg .u64 t; cvta.to.shared.u64 t, %1; cvt.u32.u64 %0, t; }" : "=r"(a) : "l"(p));
    return a;
}
__device__ __forceinline__ void mma16816(float c[4], const uint32_t a[4],
                                         uint32_t b0, uint32_t b1) {
    asm volatile(
        "mma.sync.aligned.m16n8k16.row.col.f32.f16.f16.f32 "
        "{%0,%1,%2,%3}, {%4,%5,%6,%7}, {%8,%9}, {%0,%1,%2,%3};"
        : "+f"(c[0]), "+f"(c[1]), "+f"(c[2]), "+f"(c[3])
        : "r"(a[0]), "r"(a[1]), "r"(a[2]), "r"(a[3]), "r"(b0), "r"(b1));
}
__device__ __forceinline__ void mma16816h(uint32_t c[2], const uint32_t a[4],
                                          uint32_t b0, uint32_t b1) {
    asm volatile(
        "mma.sync.aligned.m16n8k16.row.col.f16.f16.f16.f16 "
        "{%0,%1}, {%2,%3,%4,%5}, {%6,%7}, {%0,%1};"
        : "+r"(c[0]), "+r"(c[1])
        : "r"(a[0]), "r"(a[1]), "r"(a[2]), "r"(a[3]), "r"(b0), "r"(b1));
}
__device__ __forceinline__ void ldsm4(uint32_t r[4], uint32_t addr) {
    asm volatile("ldmatrix.sync.aligned.m8n8.x4.shared.b16 {%0,%1,%2,%3}, [%4];"
        : "=r"(r[0]), "=r"(r[1]), "=r"(r[2]), "=r"(r[3]) : "r"(addr));
}
__device__ __forceinline__ uint32_t sq2(uint32_t a) {
    __half2 h = *(__half2*)&a;
    h = __hmul2(h, h);
    return *(uint32_t*)&h;
}

// write one fp16 weight into the swizzled smem W tile
__device__ __forceinline__ void put_w(char* smc, int row, int d, float v) {
    const int sg = d >> 3;
    const uint32_t off = (uint32_t)(row * 256 + ((sg ^ (row & 7)) << 4) + (d & 7) * 2);
    *(__half*)(smc + SM_W + off) = __float2half_rn(v);
}

// ---------------------------------------------------------------------------
// Inline per-component precompute: one warp, one component k (verified math).
// ---------------------------------------------------------------------------
__device__ void precompute_comp(char* smc, int k, int lane,
                                const float* __restrict__ MU,
                                const float* __restrict__ A,
                                const float* __restrict__ Dm,
                                const float* __restrict__ PI)
{
    float s[22];
#pragma unroll
    for (int j = 0; j < 22; j++) s[j] = 0.f;

#pragma unroll
    for (int i = 0; i < 4; i++) {
        const int d = lane + 32 * i;
        const float Dv = Dm[k * DDIM + d];
        const float iD = 1.0f / (Dv * Dv);
        const float mu = MU[k * DDIM + d];
        float a[LDIM], B[LDIM];
#pragma unroll
        for (int l = 0; l < LDIM; l++) {
            a[l] = A[(k * DDIM + d) * LDIM + l];
            B[l] = iD * a[l];
        }
        int idx = 0;
#pragma unroll
        for (int l = 0; l < LDIM; l++)
#pragma unroll
            for (int m = 0; m < LDIM; m++)
                s[idx++] += a[l] * B[m];
#pragma unroll
        for (int m = 0; m < LDIM; m++)
            s[idx++] += mu * B[m];
        s[20] += iD * mu * mu;
        s[21] += 2.0f * logf(Dv);
    }

#pragma unroll
    for (int j = 0; j < 22; j++)
#pragma unroll
        for (int o = 16; o; o >>= 1)
            s[j] += __shfl_xor_sync(0xffffffffu, s[j], o);

    float Lm[LDIM][LDIM], bmu[LDIM];
#pragma unroll
    for (int l = 0; l < LDIM; l++)
#pragma unroll
        for (int m = 0; m < LDIM; m++)
            Lm[l][m] = s[l * LDIM + m] + (l == m ? 1.0f : 0.0f);
#pragma unroll
    for (int m = 0; m < LDIM; m++) bmu[m] = s[16 + m];
    const float tc  = s[20];
    const float sld = s[21];

    float G[LDIM][LDIM] = {};
#pragma unroll
    for (int i = 0; i < LDIM; i++) {
#pragma unroll
        for (int j = 0; j <= i; j++) {
            float v = Lm[i][j];
#pragma unroll
            for (int p = 0; p < LDIM; p++)
                if (p < j) v -= G[i][p] * G[j][p];
            if (i == j) G[i][i] = sqrtf(v);
            else        G[i][j] = v / G[j][j];
        }
    }
    float logdetL = 0.f;
#pragma unroll
    for (int i = 0; i < LDIM; i++) logdetL += 2.0f * logf(G[i][i]);

    float U[LDIM][LDIM] = {};
#pragma unroll
    for (int j = 0; j < LDIM; j++) {
        U[j][j] = 1.0f / G[j][j];
#pragma unroll
        for (int i = 0; i < LDIM; i++) {
            if (i > j) {
                float v = 0.f;
#pragma unroll
                for (int p = 0; p < LDIM; p++)
                    if (p >= j && p < i) v += G[i][p] * U[p][j];
                U[i][j] = -v / G[i][i];
            }
        }
    }

    if (lane == 0) {
        float* c = (float*)(smc + SM_C);
        const float LOG2PI = 1.8378770664093454835606594728112f;
        c[k] = PI[k] - 0.5f * ((float)DDIM * LOG2PI + logdetL + sld + tc);
        float bp[LDIM];
#pragma unroll
        for (int l = 0; l < LDIM; l++) {
            float v = 0.f;
#pragma unroll
            for (int m = 0; m <= l; m++) v += U[l][m] * bmu[m];
            bp[l] = v;
        }
        c[32 + k]  = bp[0]; c[64 + k]  = bp[1];
        c[96 + k]  = bp[2]; c[128 + k] = bp[3];
    }

#pragma unroll
    for (int i = 0; i < 4; i++) {
        const int d = lane + 32 * i;
        const float Dv = Dm[k * DDIM + d];
        const float iD = 1.0f / (Dv * Dv);
        const float mu = MU[k * DDIM + d];
        float B[LDIM];
#pragma unroll
        for (int l = 0; l < LDIM; l++)
            B[l] = iD * A[(k * DDIM + d) * LDIM + l];
        float Bp[LDIM];
#pragma unroll
        for (int l = 0; l < LDIM; l++) {
            float v = 0.f;
#pragma unroll
            for (int m = 0; m <= l; m++) v += U[l][m] * B[m];
            Bp[l] = v;
        }
        put_w(smc, k, d, iD * mu);
#pragma unroll
        for (int j = 0; j < LDIM; j++)
            put_w(smc, 32 + 32 * j + k, d, Bp[j]);
        put_w(smc, 160 + k, d, -0.5f * iD);
    }
}

// ---------------------------------------------------------------------------
// Single persistent kernel: inline precompute, then 256-row-tile GEMM loop.
// Staging fully prefetched in 4 batches of 2 slots (no exposed DRAM latency).
// ---------------------------------------------------------------------------
__global__ void __launch_bounds__(TPB, 1)
mfa_mma(const float* __restrict__ x, float* __restrict__ out, int N, int ntiles,
        const float* __restrict__ MU, const float* __restrict__ A,
        const float* __restrict__ Dm, const float* __restrict__ PI)
{
    extern __shared__ char smc[];
    const int tid  = threadIdx.x;
    const int lane = tid & 31;
    const int w    = tid >> 5;
    const int wm   = w & 7;         // row group (32 rows)
    const int wk   = w >> 3;        // component half (16 comps)
    const int qr   = lane >> 2;     // 0..7
    const int qc   = lane & 3;      // 0..3
    const int rin  = lane & 7;
    const int mat  = lane >> 3;     // 0..3

    const uint32_t sb = smem_u32(smc);

    // ---- inline precompute: warp w handles components 2w, 2w+1 ------------
    precompute_comp(smc, 2 * w,     lane, MU, A, Dm, PI);
    precompute_comp(smc, 2 * w + 1, lane, MU, A, Dm, PI);

    const float* cst = (const float*)(smc + SM_C);
    const uint32_t b_pre = sb + SM_W
        + (uint32_t)(wk * 16 + (mat >> 1) * 8 + rin) * 256u;
    uint32_t a_off[2];
#pragma unroll
    for (int mt = 0; mt < 2; mt++)
        a_off[mt] = (uint32_t)(wm * 32 + mt * 16 + (mat & 1) * 8 + rin) * 256u;

    // staging constants: slot j (0..7) -> row = base_r + 32j, off = base_off + 8192j
    const int base_r  = tid >> 4;
    const int st_s    = tid & 15;
    const uint32_t base_off =
        (uint32_t)(base_r * 256 + ((st_s ^ (base_r & 7)) << 4));

    // ---- prologue: load first tile into buffer 0 --------------------------
    {
        const int row0 = blockIdx.x * ROWS_TILE;
#pragma unroll
        for (int j = 0; j < 8; j++) {
            int row = row0 + base_r + 32 * j;
            row = row < N ? row : N - 1;
            const float4* p = (const float4*)x + (size_t)row * 32 + st_s * 2;
            const float4 v0 = __ldg(p), v1 = __ldg(p + 1);
            uint4 hx;
            hx.x = h2pack(v0.x, v0.y); hx.y = h2pack(v0.z, v0.w);
            hx.z = h2pack(v1.x, v1.y); hx.w = h2pack(v1.z, v1.w);
            *(uint4*)(smc + SM_X0 + base_off + 8192u * j) = hx;
        }
    }
    __syncthreads();

    int buf = 0;
    for (int tile = blockIdx.x; tile < ntiles; tile += gridDim.x) {
        const int row0 = tile * ROWS_TILE;
        const uint32_t xb_base = sb + (buf ? SM_X1 : SM_X0);
        char* nxt = smc + (buf ? SM_X0 : SM_X1);
        const int row0n = row0 + gridDim.x * ROWS_TILE;

        // staged batch: 2 slots = 4 float4 (16 regs), fully prefetched
        float4 sv[4];
#pragma unroll
        for (int sl = 0; sl < 2; sl++) {
            int row = row0n + base_r + 32 * sl;
            row = row < N ? row : N - 1;
            const float4* p = (const float4*)x + (size_t)row * 32 + st_s * 2;
            sv[2 * sl]     = __ldg(p);
            sv[2 * sl + 1] = __ldg(p + 1);
        }

        // ---- GEMM: accS fp32 (s2 + folded s1); accZ fp16 (z groups) -------
        float    accS[2][2][4];
        uint32_t accZ[2][4][2][2];
#pragma unroll
        for (int mt = 0; mt < 2; mt++) {
#pragma unroll
            for (int hi = 0; hi < 2; hi++)
#pragma unroll
                for (int e = 0; e < 4; e++) accS[mt][hi][e] = 0.f;
#pragma unroll
            for (int jj = 0; jj < 4; jj++)
#pragma unroll
                for (int hi = 0; hi < 2; hi++) {
                    accZ[mt][jj][hi][0] = 0u;
                    accZ[mt][jj][hi][1] = 0u;
                }
        }

#pragma unroll
        for (int ch = 0; ch < 8; ch++) {
            const uint32_t xa = (((uint32_t)(ch * 2 + (mat >> 1))) ^ (uint32_t)rin) << 4;
            const uint32_t xb = (((uint32_t)(ch * 2 + (mat & 1)))  ^ (uint32_t)rin) << 4;

            // A fragments + early x^2 (fma pipe, hides B ldsm latency)
            uint32_t ax[2][4];
            ldsm4(ax[0], xb_base + a_off[0] + xa);
            ldsm4(ax[1], xb_base + a_off[1] + xa);

            // s1-group B issued early; consumed last
            uint32_t b5[4];
            ldsm4(b5, b_pre + 5u * 8192u + xb);

            uint32_t aq[2][4];
#pragma unroll
            for (int j = 0; j < 4; j++) {
                aq[0][j] = sq2(ax[0][j]);
                aq[1][j] = sq2(ax[1][j]);
            }

            // g0: s2 (fp32 acc)
            {
                uint32_t b[4];
                ldsm4(b, b_pre + xb);
                mma16816(accS[0][0], ax[0], b[0], b[1]);
                mma16816(accS[0][1], ax[0], b[2], b[3]);
                mma16816(accS[1][0], ax[1], b[0], b[1]);
                mma16816(accS[1][1], ax[1], b[2], b[3]);
            }
            // z groups (fp16 acc)
#pragma unroll
            for (int jj = 0; jj < 4; jj++) {
                uint32_t b[4];
                ldsm4(b, b_pre + (uint32_t)(1 + jj) * 8192u + xb);
                mma16816h(accZ[0][jj][0], ax[0], b[0], b[1]);
                mma16816h(accZ[0][jj][1], ax[0], b[2], b[3]);
                mma16816h(accZ[1][jj][0], ax[1], b[0], b[1]);
                mma16816h(accZ[1][jj][1], ax[1], b[2], b[3]);
            }
            // s1 folded (-0.5*iD), fp32 acc into accS
            mma16816(accS[0][0], aq[0], b5[0], b5[1]);
            mma16816(accS[0][1], aq[0], b5[2], b5[3]);
            mma16816(accS[1][0], aq[1], b5[0], b5[1]);
            mma16816(accS[1][1], aq[1], b5[2], b5[3]);

            // staging: at odd chunks drain the prefetched batch (staged ~2
            // chunks earlier -> DRAM latency covered), then prefetch next.
            if (ch & 1) {
                const int b0 = ch >> 1;              // batch 0..3
#pragma unroll
                for (int sl = 0; sl < 2; sl++) {
                    const float4 v0 = sv[2 * sl], v1 = sv[2 * sl + 1];
                    uint4 hx;
                    hx.x = h2pack(v0.x, v0.y); hx.y = h2pack(v0.z, v0.w);
                    hx.z = h2pack(v1.x, v1.y); hx.w = h2pack(v1.z, v1.w);
                    *(uint4*)(nxt + base_off + 8192u * (2 * b0 + sl)) = hx;
                }
                if (b0 < 3) {
#pragma unroll
                    for (int sl = 0; sl < 2; sl++) {
                        int row = row0n + base_r + 32 * (2 * b0 + 2 + sl);
                        row = row < N ? row : N - 1;
                        const float4* p = (const float4*)x + (size_t)row * 32 + st_s * 2;
                        sv[2 * sl]     = __ldg(p);
                        sv[2 * sl + 1] = __ldg(p + 1);
                    }
                }
            }
        }

        // ---- partial epilogue: common max, then exp ------------------------
        float2* sP = (float2*)(smc + SM_P + (buf ? 4096 : 0));
#pragma unroll
        for (int mt = 0; mt < 2; mt++) {
#pragma unroll
            for (int h = 0; h < 2; h++) {
                float ll[4];
#pragma unroll
                for (int hi = 0; hi < 2; hi++) {
#pragma unroll
                    for (int p = 0; p < 2; p++) {
                        const int k = wk * 16 + hi * 8 + 2 * qc + p;
                        const int e = 2 * h + p;
                        float v = cst[k] + accS[mt][hi][e];
#pragma unroll
                        for (int jj = 0; jj < 4; jj++) {
                            const __half2 hz = *(const __half2*)&accZ[mt][jj][hi][h];
                            const float2 fz = __half22float2(hz);
                            const float z = (p ? fz.y : fz.x)
                                          - cst[32 + 32 * jj + k];
                            v = fmaf(0.5f * z, z, v);
                        }
                        ll[hi * 2 + p] = v;
                    }
                }
                float mx = fmaxf(fmaxf(ll[0], ll[1]), fmaxf(ll[2], ll[3]));
#pragma unroll
                for (int off = 1; off <= 2; off <<= 1)
                    mx = fmaxf(mx, __shfl_xor_sync(0xffffffffu, mx, off));
                float sum = __expf(ll[0] - mx) + __expf(ll[1] - mx)
                          + __expf(ll[2] - mx) + __expf(ll[3] - mx);
#pragma unroll
                for (int off = 1; off <= 2; off <<= 1)
                    sum += __shfl_xor_sync(0xffffffffu, sum, off);

                if (qc == 0)
                    sP[wk * 256 + wm * 32 + mt * 16 + qr + 8 * h]
                        = make_float2(mx, sum);
            }
        }
        __syncthreads();   // covers: sP writes, next-buffer STS, cur-buffer reads

        // ---- combine the two component halves, write out ------------------
        if (tid < 256) {
            const float2 a = sP[tid];
            const float2 b = sP[256 + tid];
            const float m = fmaxf(a.x, b.x);
            const float s = a.y * __expf(a.x - m) + b.y * __expf(b.x - m);
            const int row = row0 + tid;
            if (row < N) out[row] = m + __logf(s);
        }
        buf ^= 1;
    }
}

// ---------------------------------------------------------------------------
extern "C" void kernel_launch(void* const* d_in, const int* in_sizes, int n_in,
                              void* d_out, int out_size)
{
    const float* x  = (const float*)d_in[0];
    const float* MU = (const float*)d_in[1];
    const float* A  = (const float*)d_in[2];
    const float* Dm = (const float*)d_in[3];
    const float* PI = (const float*)d_in[4];
    float* out = (float*)d_out;

    const int N = in_sizes[0] / DDIM;
    const int ntiles = (N + ROWS_TILE - 1) / ROWS_TILE;

    int nsm = 148;
    cudaDeviceGetAttribute(&nsm, cudaDevAttrMultiProcessorCount, 0);
    if (nsm <= 0) nsm = 148;
    int grid = nsm < ntiles ? nsm : ntiles;

    cudaFuncSetAttribute(mfa_mma, cudaFuncAttributeMaxDynamicSharedMemorySize,
                         SMEM_TOTAL);

    mfa_mma<<<grid, TPB, SMEM_TOTAL>>>(x, out, N, ntiles, MU, A, Dm, PI);
}

// round 14
// speedup vs baseline: 1.0164x; 1.0164x over previous
#include <cuda_runtime.h>
#include <math.h>
#include <float.h>
#include <stdint.h>
#include <cuda_fp16.h>

#define KCOMP 32
#define DDIM  128
#define LDIM  4
#define TPB   512
#define ROWS_TILE 256

// smem byte offsets (~185KB, 1 CTA/SM, 512 threads)
#define SM_W   0         // weights: 192 rows x 256B (fp16) = 49152
#define SM_X0  49152     // x tile buffer 0: 256 x 256B = 65536
#define SM_X1  114688    // x tile buffer 1
#define SM_C   180224    // cst[32] + bm[4][32] floats = 640
#define SM_P   180864    // sP: 2 x 512 float2 = 8192
#define SMEM_TOTAL 189056

// ---- helpers --------------------------------------------------------------
__device__ __forceinline__ uint32_t h2pack(float a, float b) {
    __half2 h = __floats2half2_rn(a, b);
    return *(uint32_t*)&h;
}
__device__ __forceinline__ uint32_t smem_u32(const void* p) {
    uint32_t a;
    asm("{ .reg .u64 t; cvta.to.shared.u64 t, %1; cvt.u32.u64 %0, t; }" : "=r"(a) : "l"(p));
    return a;
}
__device__ __forceinline__ void mma16816(float c[4], const uint32_t a[4],
                                         uint32_t b0, uint32_t b1) {
    asm volatile(
        "mma.sync.aligned.m16n8k16.row.col.f32.f16.f16.f32 "
        "{%0,%1,%2,%3}, {%4,%5,%6,%7}, {%8,%9}, {%0,%1,%2,%3};"
        : "+f"(c[0]), "+f"(c[1]), "+f"(c[2]), "+f"(c[3])
        : "r"(a[0]), "r"(a[1]), "r"(a[2]), "r"(a[3]), "r"(b0), "r"(b1));
}
__device__ __forceinline__ void mma16816h(uint32_t c[2], const uint32_t a[4],
                                          uint32_t b0, uint32_t b1) {
    asm volatile(
        "mma.sync.aligned.m16n8k16.row.col.f16.f16.f16.f16 "
        "{%0,%1}, {%2,%3,%4,%5}, {%6,%7}, {%0,%1};"
        : "+r"(c[0]), "+r"(c[1])
        : "r"(a[0]), "r"(a[1]), "r"(a[2]), "r"(a[3]), "r"(b0), "r"(b1));
}
__device__ __forceinline__ void ldsm4(uint32_t r[4], uint32_t addr) {
    asm volatile("ldmatrix.sync.aligned.m8n8.x4.shared.b16 {%0,%1,%2,%3}, [%4];"
        : "=r"(r[0]), "=r"(r[1]), "=r"(r[2]), "=r"(r[3]) : "r"(addr));
}
__device__ __forceinline__ uint32_t sq2(uint32_t a) {
    __half2 h = *(__half2*)&a;
    h = __hmul2(h, h);
    return *(uint32_t*)&h;
}
// packed fp16x2 exp2 via one MUFU
__device__ __forceinline__ uint32_t ex2h2(uint32_t a) {
    uint32_t r;
    asm("ex2.approx.f16x2 %0, %1;" : "=r"(r) : "r"(a));
    return r;
}

// write one fp16 weight into the swizzled smem W tile
__device__ __forceinline__ void put_w(char* smc, int row, int d, float v) {
    const int sg = d >> 3;
    const uint32_t off = (uint32_t)(row * 256 + ((sg ^ (row & 7)) << 4) + (d & 7) * 2);
    *(__half*)(smc + SM_W + off) = __float2half_rn(v);
}

// ---------------------------------------------------------------------------
// Inline per-component precompute: one warp, one component k (verified math).
// ---------------------------------------------------------------------------
__device__ void precompute_comp(char* smc, int k, int lane,
                                const float* __restrict__ MU,
                                const float* __restrict__ A,
                                const float* __restrict__ Dm,
                                const float* __restrict__ PI)
{
    float s[22];
#pragma unroll
    for (int j = 0; j < 22; j++) s[j] = 0.f;

#pragma unroll
    for (int i = 0; i < 4; i++) {
        const int d = lane + 32 * i;
        const float Dv = Dm[k * DDIM + d];
        const float iD = 1.0f / (Dv * Dv);
        const float mu = MU[k * DDIM + d];
        float a[LDIM], B[LDIM];
#pragma unroll
        for (int l = 0; l < LDIM; l++) {
            a[l] = A[(k * DDIM + d) * LDIM + l];
            B[l] = iD * a[l];
        }
        int idx = 0;
#pragma unroll
        for (int l = 0; l < LDIM; l++)
#pragma unroll
            for (int m = 0; m < LDIM; m++)
                s[idx++] += a[l] * B[m];
#pragma unroll
        for (int m = 0; m < LDIM; m++)
            s[idx++] += mu * B[m];
        s[20] += iD * mu * mu;
        s[21] += 2.0f * logf(Dv);
    }

#pragma unroll
    for (int j = 0; j < 22; j++)
#pragma unroll
        for (int o = 16; o; o >>= 1)
            s[j] += __shfl_xor_sync(0xffffffffu, s[j], o);

    float Lm[LDIM][LDIM], bmu[LDIM];
#pragma unroll
    for (int l = 0; l < LDIM; l++)
#pragma unroll
        for (int m = 0; m < LDIM; m++)
            Lm[l][m] = s[l * LDIM + m] + (l == m ? 1.0f : 0.0f);
#pragma unroll
    for (int m = 0; m < LDIM; m++) bmu[m] = s[16 + m];
    const float tc  = s[20];
    const float sld = s[21];

    float G[LDIM][LDIM] = {};
#pragma unroll
    for (int i = 0; i < LDIM; i++) {
#pragma unroll
        for (int j = 0; j <= i; j++) {
            float v = Lm[i][j];
#pragma unroll
            for (int p = 0; p < LDIM; p++)
                if (p < j) v -= G[i][p] * G[j][p];
            if (i == j) G[i][i] = sqrtf(v);
            else        G[i][j] = v / G[j][j];
        }
    }
    float logdetL = 0.f;
#pragma unroll
    for (int i = 0; i < LDIM; i++) logdetL += 2.0f * logf(G[i][i]);

    float U[LDIM][LDIM] = {};
#pragma unroll
    for (int j = 0; j < LDIM; j++) {
        U[j][j] = 1.0f / G[j][j];
#pragma unroll
        for (int i = 0; i < LDIM; i++) {
            if (i > j) {
                float v = 0.f;
#pragma unroll
                for (int p = 0; p < LDIM; p++)
                    if (p >= j && p < i) v += G[i][p] * U[p][j];
                U[i][j] = -v / G[i][i];
            }
        }
    }

    if (lane == 0) {
        float* c = (float*)(smc + SM_C);
        const float LOG2PI = 1.8378770664093454835606594728112f;
        c[k] = PI[k] - 0.5f * ((float)DDIM * LOG2PI + logdetL + sld + tc);
        float bp[LDIM];
#pragma unroll
        for (int l = 0; l < LDIM; l++) {
            float v = 0.f;
#pragma unroll
            for (int m = 0; m <= l; m++) v += U[l][m] * bmu[m];
            bp[l] = v;
        }
        c[32 + k]  = bp[0]; c[64 + k]  = bp[1];
        c[96 + k]  = bp[2]; c[128 + k] = bp[3];
    }

#pragma unroll
    for (int i = 0; i < 4; i++) {
        const int d = lane + 32 * i;
        const float Dv = Dm[k * DDIM + d];
        const float iD = 1.0f / (Dv * Dv);
        const float mu = MU[k * DDIM + d];
        float B[LDIM];
#pragma unroll
        for (int l = 0; l < LDIM; l++)
            B[l] = iD * A[(k * DDIM + d) * LDIM + l];
        float Bp[LDIM];
#pragma unroll
        for (int l = 0; l < LDIM; l++) {
            float v = 0.f;
#pragma unroll
            for (int m = 0; m <= l; m++) v += U[l][m] * B[m];
            Bp[l] = v;
        }
        put_w(smc, k, d, iD * mu);
#pragma unroll
        for (int j = 0; j < LDIM; j++)
            put_w(smc, 32 + 32 * j + k, d, Bp[j]);
        put_w(smc, 160 + k, d, -0.5f * iD);
    }
}

// ---------------------------------------------------------------------------
// Single persistent kernel (R12 structure): inline precompute + tile loop.
// Epilogue partial exps via ex2.approx.f16x2 (one MUFU per comp pair).
// ---------------------------------------------------------------------------
__global__ void __launch_bounds__(TPB, 1)
mfa_mma(const float* __restrict__ x, float* __restrict__ out, int N, int ntiles,
        const float* __restrict__ MU, const float* __restrict__ A,
        const float* __restrict__ Dm, const float* __restrict__ PI)
{
    extern __shared__ char smc[];
    const int tid  = threadIdx.x;
    const int lane = tid & 31;
    const int w    = tid >> 5;
    const int wm   = w & 7;         // row group (32 rows)
    const int wk   = w >> 3;        // component half (16 comps)
    const int qr   = lane >> 2;     // 0..7
    const int qc   = lane & 3;      // 0..3
    const int rin  = lane & 7;
    const int mat  = lane >> 3;     // 0..3

    const uint32_t sb = smem_u32(smc);

    // ---- inline precompute: warp w handles components 2w, 2w+1 ------------
    precompute_comp(smc, 2 * w,     lane, MU, A, Dm, PI);
    precompute_comp(smc, 2 * w + 1, lane, MU, A, Dm, PI);

    const float* cst = (const float*)(smc + SM_C);
    const uint32_t b_pre = sb + SM_W
        + (uint32_t)(wk * 16 + (mat >> 1) * 8 + rin) * 256u;
    uint32_t a_off[2];
#pragma unroll
    for (int mt = 0; mt < 2; mt++)
        a_off[mt] = (uint32_t)(wm * 32 + mt * 16 + (mat & 1) * 8 + rin) * 256u;

    // staging constants: slot j (0..7) -> row = base_r + 32j, off = base_off + 8192j
    const int base_r  = tid >> 4;
    const int st_s    = tid & 15;
    const uint32_t base_off =
        (uint32_t)(base_r * 256 + ((st_s ^ (base_r & 7)) << 4));

    // ---- prologue: load first tile into buffer 0 --------------------------
    {
        const int row0 = blockIdx.x * ROWS_TILE;
#pragma unroll
        for (int j = 0; j < 8; j++) {
            int row = row0 + base_r + 32 * j;
            row = row < N ? row : N - 1;
            const float4* p = (const float4*)x + (size_t)row * 32 + st_s * 2;
            const float4 v0 = __ldg(p), v1 = __ldg(p + 1);
            uint4 hx;
            hx.x = h2pack(v0.x, v0.y); hx.y = h2pack(v0.z, v0.w);
            hx.z = h2pack(v1.x, v1.y); hx.w = h2pack(v1.z, v1.w);
            *(uint4*)(smc + SM_X0 + base_off + 8192u * j) = hx;
        }
    }
    __syncthreads();

    int buf = 0;
    for (int tile = blockIdx.x; tile < ntiles; tile += gridDim.x) {
        const int row0 = tile * ROWS_TILE;
        const uint32_t xb_base = sb + (buf ? SM_X1 : SM_X0);
        char* nxt = smc + (buf ? SM_X0 : SM_X1);
        const int row0n = row0 + gridDim.x * ROWS_TILE;

        // staged pair (2 x float4 = 8 regs)
        float4 sv0, sv1;
        {
            int row = row0n + base_r;
            row = row < N ? row : N - 1;
            const float4* p = (const float4*)x + (size_t)row * 32 + st_s * 2;
            sv0 = __ldg(p); sv1 = __ldg(p + 1);
        }

        // ---- GEMM: accS fp32 (s2 + folded s1); accZ fp16 (z groups) -------
        float    accS[2][2][4];
        uint32_t accZ[2][4][2][2];
#pragma unroll
        for (int mt = 0; mt < 2; mt++) {
#pragma unroll
            for (int hi = 0; hi < 2; hi++)
#pragma unroll
                for (int e = 0; e < 4; e++) accS[mt][hi][e] = 0.f;
#pragma unroll
            for (int jj = 0; jj < 4; jj++)
#pragma unroll
                for (int hi = 0; hi < 2; hi++) {
                    accZ[mt][jj][hi][0] = 0u;
                    accZ[mt][jj][hi][1] = 0u;
                }
        }

#pragma unroll
        for (int ch = 0; ch < 8; ch++) {
            const uint32_t xa = (((uint32_t)(ch * 2 + (mat >> 1))) ^ (uint32_t)rin) << 4;
            const uint32_t xb = (((uint32_t)(ch * 2 + (mat & 1)))  ^ (uint32_t)rin) << 4;

            uint32_t ax[2][4];
            ldsm4(ax[0], xb_base + a_off[0] + xa);
            ldsm4(ax[1], xb_base + a_off[1] + xa);

            // g0: s2 (fp32 acc)
            {
                uint32_t b[4];
                ldsm4(b, b_pre + xb);
                mma16816(accS[0][0], ax[0], b[0], b[1]);
                mma16816(accS[0][1], ax[0], b[2], b[3]);
                mma16816(accS[1][0], ax[1], b[0], b[1]);
                mma16816(accS[1][1], ax[1], b[2], b[3]);
            }
            // z groups (fp16 acc)
#pragma unroll
            for (int jj = 0; jj < 4; jj++) {
                uint32_t b[4];
                ldsm4(b, b_pre + (uint32_t)(1 + jj) * 8192u + xb);
                mma16816h(accZ[0][jj][0], ax[0], b[0], b[1]);
                mma16816h(accZ[0][jj][1], ax[0], b[2], b[3]);
                mma16816h(accZ[1][jj][0], ax[1], b[0], b[1]);
                mma16816h(accZ[1][jj][1], ax[1], b[2], b[3]);
            }
            // s1 folded (-0.5*iD weights), fp32 acc into accS
            {
                uint32_t aq[2][4];
#pragma unroll
                for (int j = 0; j < 4; j++) {
                    aq[0][j] = sq2(ax[0][j]);
                    aq[1][j] = sq2(ax[1][j]);
                }
                uint32_t b[4];
                ldsm4(b, b_pre + 5u * 8192u + xb);
                mma16816(accS[0][0], aq[0], b[0], b[1]);
                mma16816(accS[0][1], aq[0], b[2], b[3]);
                mma16816(accS[1][0], aq[1], b[0], b[1]);
                mma16816(accS[1][1], aq[1], b[2], b[3]);
            }

            // staging: drain current pair, issue next pair (2 slots per step)
            if (ch & 1) {
                const int b0 = ch >> 1;              // batch 0..3 at ch=1,3,5,7
                {
                    uint4 hx;
                    hx.x = h2pack(sv0.x, sv0.y); hx.y = h2pack(sv0.z, sv0.w);
                    hx.z = h2pack(sv1.x, sv1.y); hx.w = h2pack(sv1.z, sv1.w);
                    *(uint4*)(nxt + base_off + 8192u * (2 * b0)) = hx;
                }
                {
                    int row = row0n + base_r + 32 * (2 * b0 + 1);
                    row = row < N ? row : N - 1;
                    const float4* p = (const float4*)x + (size_t)row * 32 + st_s * 2;
                    const float4 v0 = __ldg(p), v1 = __ldg(p + 1);
                    uint4 hx;
                    hx.x = h2pack(v0.x, v0.y); hx.y = h2pack(v0.z, v0.w);
                    hx.z = h2pack(v1.x, v1.y); hx.w = h2pack(v1.z, v1.w);
                    *(uint4*)(nxt + base_off + 8192u * (2 * b0 + 1)) = hx;
                }
                if (b0 < 3) {
                    int row = row0n + base_r + 32 * (2 * b0 + 2);
                    row = row < N ? row : N - 1;
                    const float4* p = (const float4*)x + (size_t)row * 32 + st_s * 2;
                    sv0 = __ldg(p); sv1 = __ldg(p + 1);
                }
            }
        }

        // ---- partial epilogue: common max, packed fp16 exp2 ----------------
        const float L2E = 1.4426950408889634f;
        float2* sP = (float2*)(smc + SM_P + (buf ? 4096 : 0));
#pragma unroll
        for (int mt = 0; mt < 2; mt++) {
#pragma unroll
            for (int h = 0; h < 2; h++) {
                float ll[4];
#pragma unroll
                for (int hi = 0; hi < 2; hi++) {
#pragma unroll
                    for (int p = 0; p < 2; p++) {
                        const int k = wk * 16 + hi * 8 + 2 * qc + p;
                        const int e = 2 * h + p;
                        float v = cst[k] + accS[mt][hi][e];
#pragma unroll
                        for (int jj = 0; jj < 4; jj++) {
                            const __half2 hz = *(const __half2*)&accZ[mt][jj][hi][h];
                            const float2 fz = __half22float2(hz);
                            const float z = (p ? fz.y : fz.x)
                                          - cst[32 + 32 * jj + k];
                            v = fmaf(0.5f * z, z, v);
                        }
                        ll[hi * 2 + p] = v;
                    }
                }
                float mx = fmaxf(fmaxf(ll[0], ll[1]), fmaxf(ll[2], ll[3]));
#pragma unroll
                for (int off = 1; off <= 2; off <<= 1)
                    mx = fmaxf(mx, __shfl_xor_sync(0xffffffffu, mx, off));

                // packed exp2: one MUFU per comp pair
                const uint32_t pa = h2pack((ll[0] - mx) * L2E, (ll[1] - mx) * L2E);
                const uint32_t pb = h2pack((ll[2] - mx) * L2E, (ll[3] - mx) * L2E);
                const __half2 es = __hadd2(*(__half2*)&(uint32_t&)(const uint32_t&)pa,
                                           *(__half2*)&(uint32_t&)(const uint32_t&)pb);
                // (the line above is replaced below with explicit ex2 calls)
                const uint32_t ea = ex2h2(pa);
                const uint32_t eb = ex2h2(pb);
                const __half2 hsum = __hadd2(*(const __half2*)&ea,
                                             *(const __half2*)&eb);
                const float2 fs = __half22float2(hsum);
                float sum = fs.x + fs.y;
                (void)es;
#pragma unroll
                for (int off = 1; off <= 2; off <<= 1)
                    sum += __shfl_xor_sync(0xffffffffu, sum, off);

                if (qc == 0)
                    sP[wk * 256 + wm * 32 + mt * 16 + qr + 8 * h]
                        = make_float2(mx, sum);
            }
        }
        __syncthreads();   // covers: sP writes, next-buffer STS, cur-buffer reads

        // ---- combine the two component halves (fp32 path), write out ------
        if (tid < 256) {
            const float2 a = sP[tid];
            const float2 b = sP[256 + tid];
            const float m = fmaxf(a.x, b.x);
            const float s = a.y * __expf(a.x - m) + b.y * __expf(b.x - m);
            const int row = row0 + tid;
            if (row < N) out[row] = m + __logf(s);
        }
        buf ^= 1;
    }
}

// ---------------------------------------------------------------------------
extern "C" void kernel_launch(void* const* d_in, const int* in_sizes, int n_in,
                              void* d_out, int out_size)
{
    const float* x  = (const float*)d_in[0];
    const float* MU = (const float*)d_in[1];
    const float* A  = (const float*)d_in[2];
    const float* Dm = (const float*)d_in[3];
    const float* PI = (const float*)d_in[4];
    float* out = (float*)d_out;

    const int N = in_sizes[0] / DDIM;
    const int ntiles = (N + ROWS_TILE - 1) / ROWS_TILE;

    int nsm = 148;
    cudaDeviceGetAttribute(&nsm, cudaDevAttrMultiProcessorCount, 0);
    if (nsm <= 0) nsm = 148;
    int grid = nsm < ntiles ? nsm : ntiles;

    cudaFuncSetAttribute(mfa_mma, cudaFuncAttributeMaxDynamicSharedMemorySize,
                         SMEM_TOTAL);

    mfa_mma<<<grid, TPB, SMEM_TOTAL>>>(x, out, N, ntiles, MU, A, Dm, PI);
}